// round 16
// baseline (speedup 1.0000x reference)
#include <cuda_runtime.h>
#include <cuda_bf16.h>

// Problem constants
#define MROWS 8192     // B*T
#define CD    256
#define FCD   1024
#define TD    1024
#define BD    8
#define HD_   64
#define NH    4
#define NL    6
#define NOUT  192
#define QB    16
#define KCH   256      // keys per chunk in attention

typedef unsigned long long ull;
typedef unsigned int u32;
typedef unsigned short u16;

// ---------------- mma.sync helpers -----------------------------------------
__device__ __forceinline__ void mma16816(float* c, const u32* a, const u32* b) {
    asm("mma.sync.aligned.m16n8k16.row.col.f32.bf16.bf16.f32 "
        "{%0,%1,%2,%3}, {%4,%5,%6,%7}, {%8,%9}, {%0,%1,%2,%3};"
        : "+f"(c[0]), "+f"(c[1]), "+f"(c[2]), "+f"(c[3])
        : "r"(a[0]), "r"(a[1]), "r"(a[2]), "r"(a[3]), "r"(b[0]), "r"(b[1]));
}
#define LDSM4(r, a) \
    asm volatile("ldmatrix.sync.aligned.m8n8.x4.shared.b16 {%0,%1,%2,%3}, [%4];" \
        : "=r"((r)[0]), "=r"((r)[1]), "=r"((r)[2]), "=r"((r)[3]) : "r"(a))
#define LDSM4T(r, a) \
    asm volatile("ldmatrix.sync.aligned.m8n8.x4.trans.shared.b16 {%0,%1,%2,%3}, [%4];" \
        : "=r"((r)[0]), "=r"((r)[1]), "=r"((r)[2]), "=r"((r)[3]) : "r"(a))

__device__ __forceinline__ u32 smem_u32(const void* p) {
    u32 a;
    asm("{ .reg .u64 t; cvta.to.shared.u64 t, %1; cvt.u32.u64 %0, t; }"
        : "=r"(a) : "l"(p));
    return a;
}

// hi/lo bf16 split of a float2 -> two packed u32
__device__ __forceinline__ void split2(float2 v, u32& hi, u32& lo) {
    __nv_bfloat162 h = __float22bfloat162_rn(v);
    float2 fh = __bfloat1622float2(h);
    __nv_bfloat162 l = __float22bfloat162_rn(make_float2(v.x - fh.x, v.y - fh.y));
    hi = *(u32*)&h;
    lo = *(u32*)&l;
}

// ---------------- scratch (device globals; no allocation allowed) ----------
__device__ float g_x[MROWS * CD];
__device__ float g_q[MROWS * CD];
__device__ float g_k[MROWS * CD];
__device__ float g_v[MROWS * CD];
__device__ float g_t[MROWS * CD];
__device__ float g_f[MROWS * FCD];

// ---------------- embedding ----------------
__global__ void embed_kernel(const float* __restrict__ emb,
                             const int* __restrict__ tok) {
    int idx = blockIdx.x * 256 + threadIdx.x;
    int m = idx >> 8;
    int c = idx & 255;
    g_x[idx] = emb[tok[m] * CD + c] * 16.0f;          // sqrt(256)
}

// ---------------- tensor-core GEMM (unchanged R10 winner) ------------------
#define SA 40
#define SB 136

__device__ __forceinline__
void gemm_mma(const float* __restrict__ A, const float* __restrict__ W,
              const float* __restrict__ bias, float* __restrict__ Y,
              int N, int K, int relu)
{
    __shared__ __nv_bfloat16 Ahi[128 * SA], Alo[128 * SA];
    __shared__ __nv_bfloat16 Bhi[32 * SB],  Blo[32 * SB];

    int tid = threadIdx.x;
    int lane = tid & 31, warp = tid >> 5;
    int wm = warp >> 2, wn = warp & 3;
    int rowBase = blockIdx.y * 128;
    int colBase = blockIdx.x * 128;

    float c[4][4][4];
#pragma unroll
    for (int mi = 0; mi < 4; mi++)
#pragma unroll
        for (int ni = 0; ni < 4; ni++)
#pragma unroll
            for (int j = 0; j < 4; j++) c[mi][ni][j] = 0.f;

    int arow = tid >> 1, akh = (tid & 1) * 16;
    int brow = tid >> 3, bn0 = (tid & 7) * 16;

    u32 aHiB = smem_u32(Ahi), aLoB = smem_u32(Alo);
    u32 bHiB = smem_u32(Bhi), bLoB = smem_u32(Blo);
    int aLdRow = lane & 15, aLdOff = (lane >> 4) << 3;
    int bLdRow = lane & 15, bLdOff = (lane >> 4) << 3;

    for (int kb = 0; kb < K; kb += 32) {
        {
            const float4* p = (const float4*)(A + (size_t)(rowBase + arow) * K + kb + akh);
            int base = arow * SA + akh;
#pragma unroll
            for (int i = 0; i < 4; i++) {
                float4 v = p[i];
                u32 h0, l0, h1, l1;
                split2(make_float2(v.x, v.y), h0, l0);
                split2(make_float2(v.z, v.w), h1, l1);
                *(u32*)&Ahi[base + i * 4]     = h0;
                *(u32*)&Ahi[base + i * 4 + 2] = h1;
                *(u32*)&Alo[base + i * 4]     = l0;
                *(u32*)&Alo[base + i * 4 + 2] = l1;
            }
        }
        {
            const float* q = W + (size_t)(kb + brow) * N + colBase + bn0;
            int base = brow * SB + bn0;
#pragma unroll
            for (int i = 0; i < 4; i++) {
                float4 v = *(const float4*)(q + i * 4);
                u32 h0, l0, h1, l1;
                split2(make_float2(v.x, v.y), h0, l0);
                split2(make_float2(v.z, v.w), h1, l1);
                *(u32*)&Bhi[base + i * 4]     = h0;
                *(u32*)&Bhi[base + i * 4 + 2] = h1;
                *(u32*)&Blo[base + i * 4]     = l0;
                *(u32*)&Blo[base + i * 4 + 2] = l1;
            }
        }
        __syncthreads();

#pragma unroll
        for (int ks = 0; ks < 2; ks++) {
            int k0 = ks * 16;
            u32 bh[8], bl[8];
#pragma unroll
            for (int t = 0; t < 2; t++) {
                u32 off = (u32)(((k0 + bLdRow) * SB + wn * 32 + t * 16 + bLdOff) * 2);
                LDSM4T(&bh[t * 4], bHiB + off);
                LDSM4T(&bl[t * 4], bLoB + off);
            }
#pragma unroll
            for (int mi = 0; mi < 4; mi++) {
                u32 off = (u32)(((wm * 64 + mi * 16 + aLdRow) * SA + k0 + aLdOff) * 2);
                u32 ah[4], al[4];
                LDSM4(ah, aHiB + off);
                LDSM4(al, aLoB + off);
#pragma unroll
                for (int ni = 0; ni < 4; ni++) {
                    mma16816(c[mi][ni], ah, &bh[ni * 2]);
                    mma16816(c[mi][ni], al, &bh[ni * 2]);
                    mma16816(c[mi][ni], ah, &bl[ni * 2]);
                }
            }
        }
        __syncthreads();
    }

#pragma unroll
    for (int mi = 0; mi < 4; mi++) {
#pragma unroll
        for (int ni = 0; ni < 4; ni++) {
            int r0 = rowBase + wm * 64 + mi * 16 + (lane >> 2);
            int cc = colBase + wn * 32 + ni * 8 + (lane & 3) * 2;
            float2 bi = *(const float2*)&bias[cc];
            float2 o0 = make_float2(c[mi][ni][0] + bi.x, c[mi][ni][1] + bi.y);
            float2 o1 = make_float2(c[mi][ni][2] + bi.x, c[mi][ni][3] + bi.y);
            if (relu) {
                o0.x = fmaxf(o0.x, 0.f); o0.y = fmaxf(o0.y, 0.f);
                o1.x = fmaxf(o1.x, 0.f); o1.y = fmaxf(o1.y, 0.f);
            }
            *(float2*)&Y[(size_t)r0 * N + cc] = o0;
            *(float2*)&Y[(size_t)(r0 + 8) * N + cc] = o1;
        }
    }
}

__global__ __launch_bounds__(256, 2)
void tgemm(const float* __restrict__ A, const float* __restrict__ W,
           const float* __restrict__ bias, float* __restrict__ Y,
           int N, int K, int relu) {
    gemm_mma(A, W, bias, Y, N, K, relu);
}

__global__ __launch_bounds__(256, 2)
void qkv_tc(const float* __restrict__ A,
            const float* __restrict__ W0, const float* __restrict__ W1,
            const float* __restrict__ W2,
            const float* __restrict__ b0, const float* __restrict__ b1,
            const float* __restrict__ b2,
            float* __restrict__ Y0, float* __restrict__ Y1, float* __restrict__ Y2) {
    const float* W = (blockIdx.z == 0) ? W0 : (blockIdx.z == 1 ? W1 : W2);
    const float* bb = (blockIdx.z == 0) ? b0 : (blockIdx.z == 1 ? b1 : b2);
    float* Y = (blockIdx.z == 0) ? Y0 : (blockIdx.z == 1 ? Y1 : Y2);
    gemm_mma(A, W, bb, Y, CD, CD, 0);
}

// ---------------- tensor-core attention, smem-staged K/V -------------------
// 512 thr = 16 warps; key chunks of 256 staged in smem (bf16 hi/lo, in-kernel
// convert). Warp w owns keys [w*16, w*16+16) of each chunk. QB=16 q/block.
// smem: sQ 1024f | sRelK 192f | sPart 256f | sInv 16f | sDiag 160f |
//       buf: union{ Khi/Klo u16[256][72] (73728B) ; sAcc f32[16*16*64] }
#define KST 72                       // chunk smem stride (64 + 8 pad)
#define ATTN_SMEM (1648 * 4 + 2 * KCH * KST * 2)

__global__ __launch_bounds__(512, 1)
void attn_tc(const float* __restrict__ Q, const float* __restrict__ Kf,
             const float* __restrict__ Vf,
             const float* __restrict__ relk, const float* __restrict__ relv,
             const int* __restrict__ lens, float* __restrict__ O) {
    extern __shared__ float sm[];
    float* sQ    = sm;                    // 1024
    float* sRelK = sQ + QB * HD_;         // 192
    float* sPart = sRelK + QB * 12;       // 256
    float* sInv  = sPart + 256;           // 16
    float* sDiag = sInv + 16;             // 160
    float* buf   = sDiag + 160;           // chunk buffer / sAcc
    u16* Khi = (u16*)buf;
    u16* Klo = Khi + KCH * KST;
    float* sAcc = buf;

    int tid = threadIdx.x;
    int lane = tid & 31, w = tid >> 5;
    int gid = lane >> 2, tid4 = lane & 3;
    int q0 = blockIdx.x * QB;
    int h  = blockIdx.y;
    int b  = blockIdx.z;
    int len = lens[b];

    u32 hiB = smem_u32(Khi), loB = smem_u32(Klo);
    int ldRow = w * 16 + (lane & 15);
    int ldOff = (lane >> 4) << 3;
    u32 adrHi = hiB + (u32)(ldRow * KST + ldOff) * 2;
    u32 adrLo = loB + (u32)(ldRow * KST + ldOff) * 2;

    // Q (scaled) to smem
    for (int i = tid; i < QB * HD_; i += 512) {
        int qq = i >> 6, d = i & 63;
        sQ[i] = Q[((size_t)(b * TD + q0 + qq) * CD) + h * HD_ + d] * 0.125f;
    }
    if (tid < 160) sDiag[tid] = 0.f;
    __syncthreads();

    // q . rel_k diagonals
    if (tid < QB * 9) {
        int qq = tid / 9, r = tid % 9;
        const float* rw = relk + r * HD_;
        float s = 0.f;
#pragma unroll
        for (int d = 0; d < HD_; d++) s += sQ[qq * HD_ + d] * rw[d];
        sRelK[qq * 12 + r] = s;
    }
    __syncthreads();

    // Q fragments hi/lo (built once)
    u32 qh[4][4], ql[4][4];
#pragma unroll
    for (int ks = 0; ks < 4; ks++) {
        int c0 = ks * 16 + tid4 * 2;
        split2(*(float2*)&sQ[gid * 64 + c0],           qh[ks][0], ql[ks][0]);
        split2(*(float2*)&sQ[(gid + 8) * 64 + c0],     qh[ks][1], ql[ks][1]);
        split2(*(float2*)&sQ[gid * 64 + c0 + 8],       qh[ks][2], ql[ks][2]);
        split2(*(float2*)&sQ[(gid + 8) * 64 + c0 + 8], qh[ks][3], ql[ks][3]);
    }

    // fill indexing: thread owns row tid>>1, dim-half (tid&1)*32
    int frow = tid >> 1, fhalf = (tid & 1) * 32;
    u16* fdh = Khi + frow * KST + fhalf;
    u16* fdl = Klo + frow * KST + fhalf;

    float o[8][4];
#pragma unroll
    for (int dt = 0; dt < 8; dt++)
#pragma unroll
        for (int j = 0; j < 4; j++) o[dt][j] = 0.f;
    float psA = 0.f, psB = 0.f;

    int qA = q0 + gid, qBq = q0 + gid + 8;
    bool qokA = qA < len, qokB = qBq < len;

    for (int ch = 0; ch < TD / KCH; ch++) {
        int ck = ch * KCH;
        // ---- fill K chunk (f32 -> bf16 hi/lo) ----
        {
            const float4* src = (const float4*)(Kf + ((size_t)(b * TD + ck + frow)) * CD + h * HD_ + fhalf);
#pragma unroll
            for (int i = 0; i < 8; i++) {
                float4 v = src[i];
                u32 h0, l0, h1, l1;
                split2(make_float2(v.x, v.y), h0, l0);
                split2(make_float2(v.z, v.w), h1, l1);
                *(u32*)(fdh + i * 4)     = h0;
                *(u32*)(fdh + i * 4 + 2) = h1;
                *(u32*)(fdl + i * 4)     = l0;
                *(u32*)(fdl + i * 4 + 2) = l1;
            }
        }
        __syncthreads();

        // ---- QK for this warp's 16 keys ----
        float c[2][4];
#pragma unroll
        for (int nt = 0; nt < 2; nt++)
#pragma unroll
            for (int j = 0; j < 4; j++) c[nt][j] = 0.f;
#pragma unroll
        for (int ks = 0; ks < 4; ks++) {
            u32 kh[4], kl[4];
            LDSM4(kh, adrHi + ks * 32);
            LDSM4(kl, adrLo + ks * 32);
            u32 b0h[2] = {kh[0], kh[2]}, b1h[2] = {kh[1], kh[3]};
            u32 b0l[2] = {kl[0], kl[2]}, b1l[2] = {kl[1], kl[3]};
            mma16816(c[0], qh[ks], b0h);
            mma16816(c[0], ql[ks], b0h);
            mma16816(c[0], qh[ks], b0l);
            mma16816(c[1], qh[ks], b1h);
            mma16816(c[1], ql[ks], b1h);
            mma16816(c[1], qh[ks], b1l);
        }

        // ---- epilogue: bias/mask/exp -> P fragments ----
        u32 pah[4], pal[4];
#pragma unroll
        for (int nt = 0; nt < 2; nt++) {
            int k0 = ck + w * 16 + nt * 8 + tid4 * 2;
            int k1 = k0 + 1;
            bool kok0 = k0 < len, kok1 = k1 < len;
            float e0 = c[nt][0], e1 = c[nt][1], e2 = c[nt][2], e3 = c[nt][3];
            int r0A = k0 - qA + 4, r1A = k1 - qA + 4;
            int r0B = k0 - qBq + 4, r1B = k1 - qBq + 4;
            if ((unsigned)r0A <= 8u) e0 += sRelK[gid * 12 + r0A];
            if ((unsigned)r1A <= 8u) e1 += sRelK[gid * 12 + r1A];
            if ((unsigned)r0B <= 8u) e2 += sRelK[(gid + 8) * 12 + r0B];
            if ((unsigned)r1B <= 8u) e3 += sRelK[(gid + 8) * 12 + r1B];
            e0 = (qokA && kok0) ? __expf(e0) : 0.f;
            e1 = (qokA && kok1) ? __expf(e1) : 0.f;
            e2 = (qokB && kok0) ? __expf(e2) : 0.f;
            e3 = (qokB && kok1) ? __expf(e3) : 0.f;
            psA += e0 + e1;
            psB += e2 + e3;
            if ((unsigned)r0A <= 8u) sDiag[gid * 9 + r0A] = e0;
            if ((unsigned)r1A <= 8u) sDiag[gid * 9 + r1A] = e1;
            if ((unsigned)r0B <= 8u) sDiag[(gid + 8) * 9 + r0B] = e2;
            if ((unsigned)r1B <= 8u) sDiag[(gid + 8) * 9 + r1B] = e3;
            split2(make_float2(e0, e1), pah[nt * 2],     pal[nt * 2]);       // rows 0-7
            split2(make_float2(e2, e3), pah[nt * 2 + 1], pal[nt * 2 + 1]);   // rows 8-15
        }
        __syncthreads();   // all QK smem reads done before V overwrites

        // ---- fill V chunk ----
        {
            const float4* src = (const float4*)(Vf + ((size_t)(b * TD + ck + frow)) * CD + h * HD_ + fhalf);
#pragma unroll
            for (int i = 0; i < 8; i++) {
                float4 v = src[i];
                u32 h0, l0, h1, l1;
                split2(make_float2(v.x, v.y), h0, l0);
                split2(make_float2(v.z, v.w), h1, l1);
                *(u32*)(fdh + i * 4)     = h0;
                *(u32*)(fdh + i * 4 + 2) = h1;
                *(u32*)(fdl + i * 4)     = l0;
                *(u32*)(fdl + i * 4 + 2) = l1;
            }
        }
        __syncthreads();

        // ---- PV: P[16q x 16k] @ V[16k x 64d] ----
        u32 pa_h[4] = {pah[0], pah[1], pah[2], pah[3]};
        u32 pa_l[4] = {pal[0], pal[1], pal[2], pal[3]};
#pragma unroll
        for (int t = 0; t < 4; t++) {
            u32 vh[4], vl[4];
            LDSM4T(vh, adrHi + (u32)(t * 16) * 2);
            LDSM4T(vl, adrLo + (u32)(t * 16) * 2);
#pragma unroll
            for (int s = 0; s < 2; s++) {
                int nt = t * 2 + s;
                mma16816(o[nt], pa_h, &vh[s * 2]);
                mma16816(o[nt], pa_l, &vh[s * 2]);
                mma16816(o[nt], pa_h, &vl[s * 2]);
            }
        }
        __syncthreads();   // PV smem reads done before next chunk fill / sAcc
    }

    // psums -> sPart
    psA += __shfl_xor_sync(0xffffffffu, psA, 1);
    psA += __shfl_xor_sync(0xffffffffu, psA, 2);
    psB += __shfl_xor_sync(0xffffffffu, psB, 1);
    psB += __shfl_xor_sync(0xffffffffu, psB, 2);
    if (tid4 == 0) {
        sPart[gid * 16 + w] = psA;
        sPart[(gid + 8) * 16 + w] = psB;
    }
    // O partials -> sAcc (aliases chunk buffer; safe after last sync)
#pragma unroll
    for (int dt = 0; dt < 8; dt++) {
        *(float2*)&sAcc[((w * 16 + gid) * 64) + dt * 8 + tid4 * 2]     =
            make_float2(o[dt][0], o[dt][1]);
        *(float2*)&sAcc[((w * 16 + gid + 8) * 64) + dt * 8 + tid4 * 2] =
            make_float2(o[dt][2], o[dt][3]);
    }
    __syncthreads();

    if (tid < QB) {
        float s = 0.f;
#pragma unroll
        for (int ww = 0; ww < 16; ww++) s += sPart[tid * 16 + ww];
        sInv[tid] = (s > 0.f) ? 1.0f / s : 0.f;
    }
    __syncthreads();

    // combine 16 warps + rel_v + write
    for (int i = tid; i < QB * HD_; i += 512) {
        int qq = i >> 6, dd = i & 63;
        float a = 0.f;
#pragma unroll
        for (int g = 0; g < 16; g++) a += sAcc[(g * 16 + qq) * 64 + dd];
        float inv = sInv[qq];
        a *= inv;
#pragma unroll
        for (int r = 0; r < 9; r++)
            a += sDiag[qq * 9 + r] * inv * relv[r * HD_ + dd];
        O[((size_t)(b * TD + q0 + qq) * CD) + h * HD_ + dd] = a;
    }
}

// ---------------- residual add + LayerNorm: warp per row -------------------
__global__ __launch_bounds__(256)
void add_ln_kernel(const float* __restrict__ a, const float* __restrict__ r,
                   const float* __restrict__ g, const float* __restrict__ bb,
                   float* __restrict__ o, const int* __restrict__ lens,
                   int domask) {
    int warp = threadIdx.x >> 5, lane = threadIdx.x & 31;
    int m = blockIdx.x * 8 + warp;
    const float4* a4 = (const float4*)(a + (size_t)m * CD);
    const float4* r4 = (const float4*)(r + (size_t)m * CD);
    float4 v0 = a4[lane * 2], v1 = a4[lane * 2 + 1];
    float4 w0 = r4[lane * 2], w1 = r4[lane * 2 + 1];
    v0.x += w0.x; v0.y += w0.y; v0.z += w0.z; v0.w += w0.w;
    v1.x += w1.x; v1.y += w1.y; v1.z += w1.z; v1.w += w1.w;
    float s = v0.x + v0.y + v0.z + v0.w + v1.x + v1.y + v1.z + v1.w;
    float q = v0.x * v0.x + v0.y * v0.y + v0.z * v0.z + v0.w * v0.w +
              v1.x * v1.x + v1.y * v1.y + v1.z * v1.z + v1.w * v1.w;
#pragma unroll
    for (int off = 16; off > 0; off >>= 1) {
        s += __shfl_xor_sync(0xffffffffu, s, off);
        q += __shfl_xor_sync(0xffffffffu, q, off);
    }
    float mean = s * (1.0f / CD);
    float var = q * (1.0f / CD) - mean * mean;
    float inv = rsqrtf(var + 1e-5f);
    float4 g0 = ((const float4*)g)[lane * 2], g1 = ((const float4*)g)[lane * 2 + 1];
    float4 b0 = ((const float4*)bb)[lane * 2], b1 = ((const float4*)bb)[lane * 2 + 1];
    float4 o0, o1;
    o0.x = (v0.x - mean) * inv * g0.x + b0.x;
    o0.y = (v0.y - mean) * inv * g0.y + b0.y;
    o0.z = (v0.z - mean) * inv * g0.z + b0.z;
    o0.w = (v0.w - mean) * inv * g0.w + b0.w;
    o1.x = (v1.x - mean) * inv * g1.x + b1.x;
    o1.y = (v1.y - mean) * inv * g1.y + b1.y;
    o1.z = (v1.z - mean) * inv * g1.z + b1.z;
    o1.w = (v1.w - mean) * inv * g1.w + b1.w;
    if (domask) {
        int bb2 = m >> 10, t = m & 1023;
        if (t >= lens[bb2]) {
            o0 = make_float4(0.f, 0.f, 0.f, 0.f);
            o1 = make_float4(0.f, 0.f, 0.f, 0.f);
        }
    }
    ((float4*)(o + (size_t)m * CD))[lane * 2] = o0;
    ((float4*)(o + (size_t)m * CD))[lane * 2 + 1] = o1;
}

// ---------------- outputs ----------------
__global__ void xout_kernel(const float* __restrict__ x, float* __restrict__ ox) {
    __shared__ float tile[32][33];
    int t0 = blockIdx.x * 32, c0 = blockIdx.y * 32, b = blockIdx.z;
    int tx = threadIdx.x, ty = threadIdx.y;
    for (int i = ty; i < 32; i += 8)
        tile[i][tx] = x[((size_t)(b * TD + t0 + i) * CD) + c0 + tx];
    __syncthreads();
    for (int i = ty; i < 32; i += 8)
        ox[((size_t)(b * CD + c0 + i) * TD) + t0 + tx] = tile[tx][i];
}

__global__ void maskout_kernel(const int* __restrict__ lens, float* __restrict__ om) {
    int idx = blockIdx.x * 256 + threadIdx.x;
    int b = idx >> 10, t = idx & 1023;
    om[idx] = (t < lens[b]) ? 1.0f : 0.0f;
}

__global__ __launch_bounds__(384)
void stats_kernel(const float* __restrict__ x, const float* __restrict__ pw,
                  const float* __restrict__ pb, const int* __restrict__ lens,
                  float* __restrict__ om, float* __restrict__ ol) {
    int m0 = blockIdx.x * 8;
    __shared__ float sx[8][CD];
    int tid = threadIdx.x;
    for (int i = tid; i < 8 * CD / 4; i += 384)
        ((float4*)sx)[i] = ((const float4*)(x + (size_t)m0 * CD))[i];
    __syncthreads();

    float acc[8];
#pragma unroll
    for (int t = 0; t < 8; t++) acc[t] = 0.f;
    const float4* w4 = (const float4*)(pw + (size_t)tid * CD);
#pragma unroll 8
    for (int i = 0; i < CD / 4; i++) {
        float4 w = w4[i];
#pragma unroll
        for (int t = 0; t < 8; t++) {
            float4 xv = *(const float4*)&sx[t][i * 4];
            acc[t] += w.x * xv.x + w.y * xv.y + w.z * xv.z + w.w * xv.w;
        }
    }
    float bias = pb[tid];
#pragma unroll
    for (int t = 0; t < 8; t++) {
        int m = m0 + t;
        int b = m >> 10, tt = m & 1023;
        float msk = (tt < lens[b]) ? 1.0f : 0.0f;
        float val = (acc[t] + bias) * msk;
        if (tid < NOUT) om[((size_t)b * NOUT + tid) * TD + tt] = val;
        else            ol[((size_t)b * NOUT + (tid - NOUT)) * TD + tt] = val;
    }
}

// ---------------- launch ----------------
extern "C" void kernel_launch(void* const* d_in, const int* in_sizes, int n_in,
                              void* d_out, int out_size) {
    const float* emb  = (const float*)d_in[0];
    const float* Wq   = (const float*)d_in[1];
    const float* Wk   = (const float*)d_in[2];
    const float* Wv   = (const float*)d_in[3];
    const float* Wo   = (const float*)d_in[4];
    const float* bq   = (const float*)d_in[5];
    const float* bk   = (const float*)d_in[6];
    const float* bv   = (const float*)d_in[7];
    const float* bo   = (const float*)d_in[8];
    const float* relk = (const float*)d_in[9];
    const float* relv = (const float*)d_in[10];
    const float* ln1g = (const float*)d_in[11];
    const float* ln1b = (const float*)d_in[12];
    const float* ln2g = (const float*)d_in[13];
    const float* ln2b = (const float*)d_in[14];
    const float* fw1  = (const float*)d_in[15];
    const float* fb1  = (const float*)d_in[16];
    const float* fw2  = (const float*)d_in[17];
    const float* fb2  = (const float*)d_in[18];
    const float* pw   = (const float*)d_in[19];
    const float* pb   = (const float*)d_in[20];
    const int*   tok  = (const int*)d_in[21];
    const int*   lens = (const int*)d_in[22];

    float* out      = (float*)d_out;
    float* out_x    = out;
    float* out_m    = out_x + (size_t)BD * CD * TD;
    float* out_logs = out_m + (size_t)BD * NOUT * TD;
    float* out_mask = out_logs + (size_t)BD * NOUT * TD;

    float *px, *pq, *pk, *pv, *pt, *pf;
    cudaGetSymbolAddress((void**)&px, g_x);
    cudaGetSymbolAddress((void**)&pq, g_q);
    cudaGetSymbolAddress((void**)&pk, g_k);
    cudaGetSymbolAddress((void**)&pv, g_v);
    cudaGetSymbolAddress((void**)&pt, g_t);
    cudaGetSymbolAddress((void**)&pf, g_f);

    cudaFuncSetAttribute(attn_tc,
                         cudaFuncAttributeMaxDynamicSharedMemorySize, ATTN_SMEM);

    embed_kernel<<<MROWS * CD / 256, 256>>>(emb, tok);

    dim3 gQKV(CD / 128, MROWS / 128, 3);
    dim3 gC(CD / 128, MROWS / 128);
    dim3 gF(FCD / 128, MROWS / 128);
    for (int i = 0; i < NL; i++) {
        const size_t wcc = (size_t)i * CD * CD;
        qkv_tc<<<gQKV, 256>>>(px, Wq + wcc, Wk + wcc, Wv + wcc,
                              bq + i * CD, bk + i * CD, bv + i * CD,
                              pq, pk, pv);
        attn_tc<<<dim3(TD / QB, NH, BD), 512, ATTN_SMEM>>>(
            pq, pk, pv,
            relk + (size_t)i * 9 * HD_, relv + (size_t)i * 9 * HD_, lens, pt);
        tgemm<<<gC, 256>>>(pt, Wo + wcc, bo + i * CD, pq, CD, CD, 0);
        add_ln_kernel<<<MROWS / 8, 256>>>(px, pq, ln1g + i * CD, ln1b + i * CD,
                                          px, lens, 0);
        tgemm<<<gF, 256>>>(px, fw1 + (size_t)i * CD * FCD, fb1 + i * FCD,
                           pf, FCD, CD, 1);
        tgemm<<<gC, 256>>>(pf, fw2 + (size_t)i * FCD * CD, fb2 + i * CD,
                           pt, CD, FCD, 0);
        add_ln_kernel<<<MROWS / 8, 256>>>(px, pt, ln2g + i * CD, ln2b + i * CD,
                                          px, lens, 1);
    }

    xout_kernel<<<dim3(TD / 32, CD / 32, BD), dim3(32, 8)>>>(px, out_x);
    maskout_kernel<<<BD * TD / 256, 256>>>(lens, out_mask);
    stats_kernel<<<MROWS / 8, 384>>>(px, pw, pb, lens, out_m, out_logs);
}

// round 17
// speedup vs baseline: 1.4822x; 1.4822x over previous
#include <cuda_runtime.h>
#include <cuda_bf16.h>

// Problem constants
#define MROWS 8192     // B*T
#define CD    256
#define FCD   1024
#define TD    1024
#define BD    8
#define HD_   64
#define NH    4
#define NL    6
#define NOUT  192
#define QB    16

typedef unsigned long long ull;
typedef unsigned int u32;
typedef unsigned short u16;

// ---------------- mma.sync helpers -----------------------------------------
__device__ __forceinline__ void mma16816(float* c, const u32* a, const u32* b) {
    asm("mma.sync.aligned.m16n8k16.row.col.f32.bf16.bf16.f32 "
        "{%0,%1,%2,%3}, {%4,%5,%6,%7}, {%8,%9}, {%0,%1,%2,%3};"
        : "+f"(c[0]), "+f"(c[1]), "+f"(c[2]), "+f"(c[3])
        : "r"(a[0]), "r"(a[1]), "r"(a[2]), "r"(a[3]), "r"(b[0]), "r"(b[1]));
}
#define LDSM4(r, a) \
    asm volatile("ldmatrix.sync.aligned.m8n8.x4.shared.b16 {%0,%1,%2,%3}, [%4];" \
        : "=r"((r)[0]), "=r"((r)[1]), "=r"((r)[2]), "=r"((r)[3]) : "r"(a))
#define LDSM4T(r, a) \
    asm volatile("ldmatrix.sync.aligned.m8n8.x4.trans.shared.b16 {%0,%1,%2,%3}, [%4];" \
        : "=r"((r)[0]), "=r"((r)[1]), "=r"((r)[2]), "=r"((r)[3]) : "r"(a))

__device__ __forceinline__ u32 smem_u32(const void* p) {
    u32 a;
    asm("{ .reg .u64 t; cvta.to.shared.u64 t, %1; cvt.u32.u64 %0, t; }"
        : "=r"(a) : "l"(p));
    return a;
}

// hi/lo bf16 split of a float2 -> two packed u32
__device__ __forceinline__ void split2(float2 v, u32& hi, u32& lo) {
    __nv_bfloat162 h = __float22bfloat162_rn(v);
    float2 fh = __bfloat1622float2(h);
    __nv_bfloat162 l = __float22bfloat162_rn(make_float2(v.x - fh.x, v.y - fh.y));
    hi = *(u32*)&h;
    lo = *(u32*)&l;
}

// ---------------- scratch (device globals; no allocation allowed) ----------
__device__ float g_x[MROWS * CD];
__device__ float g_q[MROWS * CD];
__device__ float g_k[MROWS * CD];
__device__ float g_v[MROWS * CD];
__device__ float g_t[MROWS * CD];
__device__ float g_f[MROWS * FCD];
__device__ ull g_khl[MROWS * CD / 2];    // K bf16 (hi pair | lo pair<<32), [tok][c/2]
__device__ ull g_vthl[MROWS * CD / 2];   // V^T bf16 packed, [b][c][t/2]

// ---------------- embedding ----------------
__global__ void embed_kernel(const float* __restrict__ emb,
                             const int* __restrict__ tok) {
    int idx = blockIdx.x * 256 + threadIdx.x;
    int m = idx >> 8;
    int c = idx & 255;
    g_x[idx] = emb[tok[m] * CD + c] * 16.0f;          // sqrt(256)
}

// ---------------- K convert: f32 -> packed bf16 hi/lo ----------------------
__global__ void kcvt_kernel(const float* __restrict__ src) {
    int idx = blockIdx.x * 256 + threadIdx.x;          // over MROWS*CD/2
    float2 v = ((const float2*)src)[idx];
    u32 h, l;
    split2(v, h, l);
    g_khl[idx] = (ull)h | ((ull)l << 32);
}

// ---------------- V transpose: f32 [b*T][C] -> packed bf16 [b][C][T] -------
__global__ void vtrans_kernel(const float* __restrict__ v) {
    __shared__ float tile[32][33];
    int t0 = blockIdx.x * 32, c0 = blockIdx.y * 32, b = blockIdx.z;
    int tx = threadIdx.x, ty = threadIdx.y;            // 32 x 8
    for (int i = ty; i < 32; i += 8)
        tile[i][tx] = v[(size_t)(b * TD + t0 + i) * CD + c0 + tx];
    __syncthreads();
    if (tx < 16) {
        for (int i = ty; i < 32; i += 8) {
            float x0 = tile[2 * tx][i];
            float x1 = tile[2 * tx + 1][i];
            u32 h, l;
            split2(make_float2(x0, x1), h, l);
            size_t o = ((size_t)(b * CD + c0 + i) * TD + t0 + 2 * tx) >> 1;
            g_vthl[o] = (ull)h | ((ull)l << 32);
        }
    }
}

// ---------------- tensor-core GEMM (unchanged R10 winner) ------------------
#define SA 40
#define SB 136

__device__ __forceinline__
void gemm_mma(const float* __restrict__ A, const float* __restrict__ W,
              const float* __restrict__ bias, float* __restrict__ Y,
              int N, int K, int relu)
{
    __shared__ __nv_bfloat16 Ahi[128 * SA], Alo[128 * SA];
    __shared__ __nv_bfloat16 Bhi[32 * SB],  Blo[32 * SB];

    int tid = threadIdx.x;
    int lane = tid & 31, warp = tid >> 5;
    int wm = warp >> 2, wn = warp & 3;
    int rowBase = blockIdx.y * 128;
    int colBase = blockIdx.x * 128;

    float c[4][4][4];
#pragma unroll
    for (int mi = 0; mi < 4; mi++)
#pragma unroll
        for (int ni = 0; ni < 4; ni++)
#pragma unroll
            for (int j = 0; j < 4; j++) c[mi][ni][j] = 0.f;

    int arow = tid >> 1, akh = (tid & 1) * 16;
    int brow = tid >> 3, bn0 = (tid & 7) * 16;

    u32 aHiB = smem_u32(Ahi), aLoB = smem_u32(Alo);
    u32 bHiB = smem_u32(Bhi), bLoB = smem_u32(Blo);
    int aLdRow = lane & 15, aLdOff = (lane >> 4) << 3;
    int bLdRow = lane & 15, bLdOff = (lane >> 4) << 3;

    for (int kb = 0; kb < K; kb += 32) {
        {
            const float4* p = (const float4*)(A + (size_t)(rowBase + arow) * K + kb + akh);
            int base = arow * SA + akh;
#pragma unroll
            for (int i = 0; i < 4; i++) {
                float4 v = p[i];
                u32 h0, l0, h1, l1;
                split2(make_float2(v.x, v.y), h0, l0);
                split2(make_float2(v.z, v.w), h1, l1);
                *(u32*)&Ahi[base + i * 4]     = h0;
                *(u32*)&Ahi[base + i * 4 + 2] = h1;
                *(u32*)&Alo[base + i * 4]     = l0;
                *(u32*)&Alo[base + i * 4 + 2] = l1;
            }
        }
        {
            const float* q = W + (size_t)(kb + brow) * N + colBase + bn0;
            int base = brow * SB + bn0;
#pragma unroll
            for (int i = 0; i < 4; i++) {
                float4 v = *(const float4*)(q + i * 4);
                u32 h0, l0, h1, l1;
                split2(make_float2(v.x, v.y), h0, l0);
                split2(make_float2(v.z, v.w), h1, l1);
                *(u32*)&Bhi[base + i * 4]     = h0;
                *(u32*)&Bhi[base + i * 4 + 2] = h1;
                *(u32*)&Blo[base + i * 4]     = l0;
                *(u32*)&Blo[base + i * 4 + 2] = l1;
            }
        }
        __syncthreads();

#pragma unroll
        for (int ks = 0; ks < 2; ks++) {
            int k0 = ks * 16;
            u32 bh[8], bl[8];
#pragma unroll
            for (int t = 0; t < 2; t++) {
                u32 off = (u32)(((k0 + bLdRow) * SB + wn * 32 + t * 16 + bLdOff) * 2);
                LDSM4T(&bh[t * 4], bHiB + off);
                LDSM4T(&bl[t * 4], bLoB + off);
            }
#pragma unroll
            for (int mi = 0; mi < 4; mi++) {
                u32 off = (u32)(((wm * 64 + mi * 16 + aLdRow) * SA + k0 + aLdOff) * 2);
                u32 ah[4], al[4];
                LDSM4(ah, aHiB + off);
                LDSM4(al, aLoB + off);
#pragma unroll
                for (int ni = 0; ni < 4; ni++) {
                    mma16816(c[mi][ni], ah, &bh[ni * 2]);
                    mma16816(c[mi][ni], al, &bh[ni * 2]);
                    mma16816(c[mi][ni], ah, &bl[ni * 2]);
                }
            }
        }
        __syncthreads();
    }

#pragma unroll
    for (int mi = 0; mi < 4; mi++) {
#pragma unroll
        for (int ni = 0; ni < 4; ni++) {
            int r0 = rowBase + wm * 64 + mi * 16 + (lane >> 2);
            int cc = colBase + wn * 32 + ni * 8 + (lane & 3) * 2;
            float2 bi = *(const float2*)&bias[cc];
            float2 o0 = make_float2(c[mi][ni][0] + bi.x, c[mi][ni][1] + bi.y);
            float2 o1 = make_float2(c[mi][ni][2] + bi.x, c[mi][ni][3] + bi.y);
            if (relu) {
                o0.x = fmaxf(o0.x, 0.f); o0.y = fmaxf(o0.y, 0.f);
                o1.x = fmaxf(o1.x, 0.f); o1.y = fmaxf(o1.y, 0.f);
            }
            *(float2*)&Y[(size_t)r0 * N + cc] = o0;
            *(float2*)&Y[(size_t)(r0 + 8) * N + cc] = o1;
        }
    }
}

__global__ __launch_bounds__(256, 2)
void tgemm(const float* __restrict__ A, const float* __restrict__ W,
           const float* __restrict__ bias, float* __restrict__ Y,
           int N, int K, int relu) {
    gemm_mma(A, W, bias, Y, N, K, relu);
}

__global__ __launch_bounds__(256, 2)
void qkv_tc(const float* __restrict__ A,
            const float* __restrict__ W0, const float* __restrict__ W1,
            const float* __restrict__ W2,
            const float* __restrict__ b0, const float* __restrict__ b1,
            const float* __restrict__ b2,
            float* __restrict__ Y0, float* __restrict__ Y1, float* __restrict__ Y2) {
    const float* W = (blockIdx.z == 0) ? W0 : (blockIdx.z == 1 ? W1 : W2);
    const float* bb = (blockIdx.z == 0) ? b0 : (blockIdx.z == 1 ? b1 : b2);
    float* Y = (blockIdx.z == 0) ? Y0 : (blockIdx.z == 1 ? Y1 : Y2);
    gemm_mma(A, W, bb, Y, CD, CD, 0);
}

// ---------------- tensor-core attention (R11 structure, packed hi/lo) ------
// 512 thr = 16 warps; warp w owns keys [w*64, w*64+64). QB=16 queries/block.
#define ATTN_SMEM ((1024 + 192 + 256 + 16 + 160 + 16384) * 4)

__global__ __launch_bounds__(512, 1)
void attn_tc(const float* __restrict__ Q,
             const ull* __restrict__ Khl, const ull* __restrict__ Vthl,
             const float* __restrict__ relk, const float* __restrict__ relv,
             const int* __restrict__ lens, float* __restrict__ O) {
    extern __shared__ float sm[];
    float* sQ    = sm;                    // 16*64
    float* sRelK = sQ + QB * HD_;         // 16*12
    float* sPart = sRelK + QB * 12;       // 16*16
    float* sInv  = sPart + 256;           // 16
    float* sDiag = sInv + 16;             // 16*9 (pad 160)
    float* sAcc  = sDiag + 160;           // 16 warps * 16 q * 64 d

    int tid = threadIdx.x;
    int lane = tid & 31, w = tid >> 5;
    int gid = lane >> 2, tid4 = lane & 3;
    int q0 = blockIdx.x * QB;
    int h  = blockIdx.y;
    int b  = blockIdx.z;
    int len = lens[b];

    // Q (scaled) to smem
    for (int i = tid; i < QB * HD_; i += 512) {
        int qq = i >> 6, d = i & 63;
        sQ[i] = Q[((size_t)(b * TD + q0 + qq) * CD) + h * HD_ + d] * 0.125f;
    }
    if (tid < 160) sDiag[tid] = 0.f;
    __syncthreads();

    // q . rel_k diagonals
    if (tid < QB * 9) {
        int qq = tid / 9, r = tid % 9;
        const float* rw = relk + r * HD_;
        float s = 0.f;
#pragma unroll
        for (int d = 0; d < HD_; d++) s += sQ[qq * HD_ + d] * rw[d];
        sRelK[qq * 12 + r] = s;
    }
    __syncthreads();

    // P fragments (built in QK epilogue, consumed by PV)
    u32 pah[4][4], pal[4][4];
    float psA, psB;
    {
        // Q fragments hi/lo from sQ
        u32 qh[4][4], ql[4][4];
#pragma unroll
        for (int ks = 0; ks < 4; ks++) {
            int c0 = ks * 16 + tid4 * 2;
            split2(*(float2*)&sQ[gid * 64 + c0],            qh[ks][0], ql[ks][0]);
            split2(*(float2*)&sQ[(gid + 8) * 64 + c0],      qh[ks][1], ql[ks][1]);
            split2(*(float2*)&sQ[gid * 64 + c0 + 8],        qh[ks][2], ql[ks][2]);
            split2(*(float2*)&sQ[(gid + 8) * 64 + c0 + 8],  qh[ks][3], ql[ks][3]);
        }

        float c[8][4];
#pragma unroll
        for (int nt = 0; nt < 8; nt++)
#pragma unroll
            for (int j = 0; j < 4; j++) c[nt][j] = 0.f;

        int keyB = w * 64 + gid;     // B-frag key row for this lane
        const ull* kp = Khl + ((((size_t)(b * TD) + keyB) * CD + h * HD_) >> 1);
#pragma unroll
        for (int ks = 0; ks < 4; ks++) {
            int dh = (ks * 16 + tid4 * 2) >> 1;
#pragma unroll
            for (int nt = 0; nt < 8; nt++) {
                const ull* p = kp + nt * 4 * CD + dh;
                ull v0 = p[0];
                ull v1 = p[4];
                u32 bf[2]  = {(u32)v0, (u32)v1};
                u32 blo[2] = {(u32)(v0 >> 32), (u32)(v1 >> 32)};
                mma16816(c[nt], qh[ks], bf);
                mma16816(c[nt], ql[ks], bf);
                mma16816(c[nt], qh[ks], blo);
            }
        }

        // epilogue: bias + mask + exp, psums, diagonals, P fragments
        psA = 0.f; psB = 0.f;
        int qA = q0 + gid, qBq = q0 + gid + 8;
        bool qokA = qA < len, qokB = qBq < len;
#pragma unroll
        for (int nt = 0; nt < 8; nt++) {
            int k0 = w * 64 + nt * 8 + tid4 * 2;
            int k1 = k0 + 1;
            bool kok0 = k0 < len, kok1 = k1 < len;
            float e0 = c[nt][0], e1 = c[nt][1], e2 = c[nt][2], e3 = c[nt][3];
            int r0A = k0 - qA + 4, r1A = k1 - qA + 4;
            int r0B = k0 - qBq + 4, r1B = k1 - qBq + 4;
            if ((unsigned)r0A <= 8u) e0 += sRelK[gid * 12 + r0A];
            if ((unsigned)r1A <= 8u) e1 += sRelK[gid * 12 + r1A];
            if ((unsigned)r0B <= 8u) e2 += sRelK[(gid + 8) * 12 + r0B];
            if ((unsigned)r1B <= 8u) e3 += sRelK[(gid + 8) * 12 + r1B];
            e0 = (qokA && kok0) ? __expf(e0) : 0.f;
            e1 = (qokA && kok1) ? __expf(e1) : 0.f;
            e2 = (qokB && kok0) ? __expf(e2) : 0.f;
            e3 = (qokB && kok1) ? __expf(e3) : 0.f;
            psA += e0 + e1;
            psB += e2 + e3;
            if ((unsigned)r0A <= 8u) sDiag[gid * 9 + r0A] = e0;
            if ((unsigned)r1A <= 8u) sDiag[gid * 9 + r1A] = e1;
            if ((unsigned)r0B <= 8u) sDiag[(gid + 8) * 9 + r0B] = e2;
            if ((unsigned)r1B <= 8u) sDiag[(gid + 8) * 9 + r1B] = e3;
            int ks2 = nt >> 1;
            int half = (nt & 1) * 2;
            split2(make_float2(e0, e1), pah[ks2][half],     pal[ks2][half]);
            split2(make_float2(e2, e3), pah[ks2][half + 1], pal[ks2][half + 1]);
        }
        // quad reduce psums (lanes sharing gid)
        psA += __shfl_xor_sync(0xffffffffu, psA, 1);
        psA += __shfl_xor_sync(0xffffffffu, psA, 2);
        psB += __shfl_xor_sync(0xffffffffu, psB, 1);
        psB += __shfl_xor_sync(0xffffffffu, psB, 2);
        if (tid4 == 0) {
            sPart[gid * 16 + w] = psA;
            sPart[(gid + 8) * 16 + w] = psB;
        }
    }
    __syncthreads();

    if (tid < QB) {
        float s = 0.f;
#pragma unroll
        for (int ww = 0; ww < 16; ww++) s += sPart[tid * 16 + ww];
        sInv[tid] = (s > 0.f) ? 1.0f / s : 0.f;
    }

    // ---- PV via mma: O_partial[16q][64d] per warp ----
    float o[8][4];
#pragma unroll
    for (int dt = 0; dt < 8; dt++)
#pragma unroll
        for (int j = 0; j < 4; j++) o[dt][j] = 0.f;

    {
        int dimB = h * HD_ + gid;
        const ull* vp = Vthl + ((((size_t)(b * CD) + dimB) * TD + w * 64) >> 1);
#pragma unroll
        for (int ks2 = 0; ks2 < 4; ks2++) {
            int kh2 = (ks2 * 16 + tid4 * 2) >> 1;
#pragma unroll
            for (int dt = 0; dt < 8; dt++) {
                const ull* p = vp + dt * 4 * TD + kh2;
                ull v0 = p[0];
                ull v1 = p[4];
                u32 bf[2]  = {(u32)v0, (u32)v1};
                u32 blo[2] = {(u32)(v0 >> 32), (u32)(v1 >> 32)};
                mma16816(o[dt], pah[ks2], bf);
                mma16816(o[dt], pal[ks2], bf);
                mma16816(o[dt], pah[ks2], blo);
            }
        }
    }
    // store partials
#pragma unroll
    for (int dt = 0; dt < 8; dt++) {
        *(float2*)&sAcc[((w * 16 + gid) * 64) + dt * 8 + tid4 * 2]     =
            make_float2(o[dt][0], o[dt][1]);
        *(float2*)&sAcc[((w * 16 + gid + 8) * 64) + dt * 8 + tid4 * 2] =
            make_float2(o[dt][2], o[dt][3]);
    }
    __syncthreads();

    // combine 16 warps + rel_v + write
    for (int i = tid; i < QB * HD_; i += 512) {
        int qq = i >> 6, dd = i & 63;
        float a = 0.f;
#pragma unroll
        for (int g = 0; g < 16; g++) a += sAcc[(g * 16 + qq) * 64 + dd];
        float inv = sInv[qq];
        a *= inv;
#pragma unroll
        for (int r = 0; r < 9; r++)
            a += sDiag[qq * 9 + r] * inv * relv[r * HD_ + dd];
        O[((size_t)(b * TD + q0 + qq) * CD) + h * HD_ + dd] = a;
    }
}

// ---------------- residual add + LayerNorm: warp per row -------------------
__global__ __launch_bounds__(256)
void add_ln_kernel(const float* __restrict__ a, const float* __restrict__ r,
                   const float* __restrict__ g, const float* __restrict__ bb,
                   float* __restrict__ o, const int* __restrict__ lens,
                   int domask) {
    int warp = threadIdx.x >> 5, lane = threadIdx.x & 31;
    int m = blockIdx.x * 8 + warp;
    const float4* a4 = (const float4*)(a + (size_t)m * CD);
    const float4* r4 = (const float4*)(r + (size_t)m * CD);
    float4 v0 = a4[lane * 2], v1 = a4[lane * 2 + 1];
    float4 w0 = r4[lane * 2], w1 = r4[lane * 2 + 1];
    v0.x += w0.x; v0.y += w0.y; v0.z += w0.z; v0.w += w0.w;
    v1.x += w1.x; v1.y += w1.y; v1.z += w1.z; v1.w += w1.w;
    float s = v0.x + v0.y + v0.z + v0.w + v1.x + v1.y + v1.z + v1.w;
    float q = v0.x * v0.x + v0.y * v0.y + v0.z * v0.z + v0.w * v0.w +
              v1.x * v1.x + v1.y * v1.y + v1.z * v1.z + v1.w * v1.w;
#pragma unroll
    for (int off = 16; off > 0; off >>= 1) {
        s += __shfl_xor_sync(0xffffffffu, s, off);
        q += __shfl_xor_sync(0xffffffffu, q, off);
    }
    float mean = s * (1.0f / CD);
    float var = q * (1.0f / CD) - mean * mean;
    float inv = rsqrtf(var + 1e-5f);
    float4 g0 = ((const float4*)g)[lane * 2], g1 = ((const float4*)g)[lane * 2 + 1];
    float4 b0 = ((const float4*)bb)[lane * 2], b1 = ((const float4*)bb)[lane * 2 + 1];
    float4 o0, o1;
    o0.x = (v0.x - mean) * inv * g0.x + b0.x;
    o0.y = (v0.y - mean) * inv * g0.y + b0.y;
    o0.z = (v0.z - mean) * inv * g0.z + b0.z;
    o0.w = (v0.w - mean) * inv * g0.w + b0.w;
    o1.x = (v1.x - mean) * inv * g1.x + b1.x;
    o1.y = (v1.y - mean) * inv * g1.y + b1.y;
    o1.z = (v1.z - mean) * inv * g1.z + b1.z;
    o1.w = (v1.w - mean) * inv * g1.w + b1.w;
    if (domask) {
        int bb2 = m >> 10, t = m & 1023;
        if (t >= lens[bb2]) {
            o0 = make_float4(0.f, 0.f, 0.f, 0.f);
            o1 = make_float4(0.f, 0.f, 0.f, 0.f);
        }
    }
    ((float4*)(o + (size_t)m * CD))[lane * 2] = o0;
    ((float4*)(o + (size_t)m * CD))[lane * 2 + 1] = o1;
}

// ---------------- outputs ----------------
__global__ void xout_kernel(const float* __restrict__ x, float* __restrict__ ox) {
    __shared__ float tile[32][33];
    int t0 = blockIdx.x * 32, c0 = blockIdx.y * 32, b = blockIdx.z;
    int tx = threadIdx.x, ty = threadIdx.y;
    for (int i = ty; i < 32; i += 8)
        tile[i][tx] = x[((size_t)(b * TD + t0 + i) * CD) + c0 + tx];
    __syncthreads();
    for (int i = ty; i < 32; i += 8)
        ox[((size_t)(b * CD + c0 + i) * TD) + t0 + tx] = tile[tx][i];
}

__global__ void maskout_kernel(const int* __restrict__ lens, float* __restrict__ om) {
    int idx = blockIdx.x * 256 + threadIdx.x;
    int b = idx >> 10, t = idx & 1023;
    om[idx] = (t < lens[b]) ? 1.0f : 0.0f;
}

__global__ __launch_bounds__(384)
void stats_kernel(const float* __restrict__ x, const float* __restrict__ pw,
                  const float* __restrict__ pb, const int* __restrict__ lens,
                  float* __restrict__ om, float* __restrict__ ol) {
    int m0 = blockIdx.x * 8;
    __shared__ float sx[8][CD];
    int tid = threadIdx.x;
    for (int i = tid; i < 8 * CD / 4; i += 384)
        ((float4*)sx)[i] = ((const float4*)(x + (size_t)m0 * CD))[i];
    __syncthreads();

    float acc[8];
#pragma unroll
    for (int t = 0; t < 8; t++) acc[t] = 0.f;
    const float4* w4 = (const float4*)(pw + (size_t)tid * CD);
#pragma unroll 8
    for (int i = 0; i < CD / 4; i++) {
        float4 w = w4[i];
#pragma unroll
        for (int t = 0; t < 8; t++) {
            float4 xv = *(const float4*)&sx[t][i * 4];
            acc[t] += w.x * xv.x + w.y * xv.y + w.z * xv.z + w.w * xv.w;
        }
    }
    float bias = pb[tid];
#pragma unroll
    for (int t = 0; t < 8; t++) {
        int m = m0 + t;
        int b = m >> 10, tt = m & 1023;
        float msk = (tt < lens[b]) ? 1.0f : 0.0f;
        float val = (acc[t] + bias) * msk;
        if (tid < NOUT) om[((size_t)b * NOUT + tid) * TD + tt] = val;
        else            ol[((size_t)b * NOUT + (tid - NOUT)) * TD + tt] = val;
    }
}

// ---------------- launch ----------------
extern "C" void kernel_launch(void* const* d_in, const int* in_sizes, int n_in,
                              void* d_out, int out_size) {
    const float* emb  = (const float*)d_in[0];
    const float* Wq   = (const float*)d_in[1];
    const float* Wk   = (const float*)d_in[2];
    const float* Wv   = (const float*)d_in[3];
    const float* Wo   = (const float*)d_in[4];
    const float* bq   = (const float*)d_in[5];
    const float* bk   = (const float*)d_in[6];
    const float* bv   = (const float*)d_in[7];
    const float* bo   = (const float*)d_in[8];
    const float* relk = (const float*)d_in[9];
    const float* relv = (const float*)d_in[10];
    const float* ln1g = (const float*)d_in[11];
    const float* ln1b = (const float*)d_in[12];
    const float* ln2g = (const float*)d_in[13];
    const float* ln2b = (const float*)d_in[14];
    const float* fw1  = (const float*)d_in[15];
    const float* fb1  = (const float*)d_in[16];
    const float* fw2  = (const float*)d_in[17];
    const float* fb2  = (const float*)d_in[18];
    const float* pw   = (const float*)d_in[19];
    const float* pb   = (const float*)d_in[20];
    const int*   tok  = (const int*)d_in[21];
    const int*   lens = (const int*)d_in[22];

    float* out      = (float*)d_out;
    float* out_x    = out;
    float* out_m    = out_x + (size_t)BD * CD * TD;
    float* out_logs = out_m + (size_t)BD * NOUT * TD;
    float* out_mask = out_logs + (size_t)BD * NOUT * TD;

    float *px, *pq, *pk, *pv, *pt, *pf;
    ull *pkhl, *pvthl;
    cudaGetSymbolAddress((void**)&px, g_x);
    cudaGetSymbolAddress((void**)&pq, g_q);
    cudaGetSymbolAddress((void**)&pk, g_k);
    cudaGetSymbolAddress((void**)&pv, g_v);
    cudaGetSymbolAddress((void**)&pt, g_t);
    cudaGetSymbolAddress((void**)&pf, g_f);
    cudaGetSymbolAddress((void**)&pkhl, g_khl);
    cudaGetSymbolAddress((void**)&pvthl, g_vthl);

    cudaFuncSetAttribute(attn_tc,
                         cudaFuncAttributeMaxDynamicSharedMemorySize, ATTN_SMEM);

    embed_kernel<<<MROWS * CD / 256, 256>>>(emb, tok);

    dim3 gQKV(CD / 128, MROWS / 128, 3);
    dim3 gC(CD / 128, MROWS / 128);
    dim3 gF(FCD / 128, MROWS / 128);
    dim3 gVT(TD / 32, CD / 32, BD);
    for (int i = 0; i < NL; i++) {
        const size_t wcc = (size_t)i * CD * CD;
        qkv_tc<<<gQKV, 256>>>(px, Wq + wcc, Wk + wcc, Wv + wcc,
                              bq + i * CD, bk + i * CD, bv + i * CD,
                              pq, pk, pv);
        kcvt_kernel<<<MROWS * CD / 512, 256>>>(pk);
        vtrans_kernel<<<gVT, dim3(32, 8)>>>(pv);
        attn_tc<<<dim3(TD / QB, NH, BD), 512, ATTN_SMEM>>>(
            pq, pkhl, pvthl,
            relk + (size_t)i * 9 * HD_, relv + (size_t)i * 9 * HD_, lens, pt);
        tgemm<<<gC, 256>>>(pt, Wo + wcc, bo + i * CD, pq, CD, CD, 0);
        add_ln_kernel<<<MROWS / 8, 256>>>(px, pq, ln1g + i * CD, ln1b + i * CD,
                                          px, lens, 0);
        tgemm<<<gF, 256>>>(px, fw1 + (size_t)i * CD * FCD, fb1 + i * FCD,
                           pf, FCD, CD, 1);
        tgemm<<<gC, 256>>>(pf, fw2 + (size_t)i * FCD * CD, fb2 + i * CD,
                           pt, CD, FCD, 0);
        add_ln_kernel<<<MROWS / 8, 256>>>(px, pt, ln2g + i * CD, ln2b + i * CD,
                                          px, lens, 1);
    }

    xout_kernel<<<gVT, dim3(32, 8)>>>(px, out_x);
    maskout_kernel<<<BD * TD / 256, 256>>>(lens, out_mask);
    stats_kernel<<<MROWS / 8, 384>>>(px, pw, pb, lens, out_m, out_logs);
}